// round 6
// baseline (speedup 1.0000x reference)
#include <cuda_runtime.h>
#include <cuda_bf16.h>
#include <cstdint>

#define BDIM 16
#define NDIM 128
#define HDIM 256

#define ASTR 264     // A smem row stride (bf16), padded: ldmatrix conflict-free
#define BSTR 40      // B smem row stride (bf16), padded (32 cols + 8)

#define A_SPL (64 * ASTR * 2)        // 33792 B per split (64 rows)
#define B_SPL (256 * BSTR * 2)       // 20480 B per split (n-chunk = 32)
#define OFF_ALO (A_SPL)
#define OFF_BHI (2 * A_SPL)                  // 67584
#define OFF_BLO (2 * A_SPL + B_SPL)          // 88064
#define MISC_OFF (2 * A_SPL + 2 * B_SPL)     // 108544
#define SMEM_REQ (MISC_OFF + 4096)           // misc needs 3616B

#define NTHR 256

// scratch
__device__ float g_xw[BDIM * NDIM * HDIM];            // inputs @ W_atom
__device__ float g_part[2 * BDIM * NDIM];             // per-CTA partial sum_j score
// bf16 hi/lo images of W_bin column-chunks: [chunk8][h=256][n=32]
__device__ __align__(16) unsigned short g_Wh[8][HDIM * 32];
__device__ __align__(16) unsigned short g_Wl[8][HDIM * 32];

// ---------------------------------------------------------------------------
__device__ __forceinline__ uint32_t smem_u32(const void* p) {
    uint32_t a;
    asm("{ .reg .u64 t; cvta.to.shared.u64 t, %1; cvt.u32.u64 %0, t; }" : "=r"(a) : "l"(p));
    return a;
}
__device__ __forceinline__ void cp_async16(uint32_t dst, const void* src) {
    asm volatile("cp.async.cg.shared.global [%0], [%1], 16;" :: "r"(dst), "l"(src));
}
__device__ __forceinline__ void ldsm_x4(uint32_t* r, uint32_t addr) {
    asm volatile("ldmatrix.sync.aligned.m8n8.x4.shared.b16 {%0,%1,%2,%3}, [%4];"
        : "=r"(r[0]), "=r"(r[1]), "=r"(r[2]), "=r"(r[3]) : "r"(addr));
}
__device__ __forceinline__ void ldsm_x4_t(uint32_t* r, uint32_t addr) {
    asm volatile("ldmatrix.sync.aligned.m8n8.x4.trans.shared.b16 {%0,%1,%2,%3}, [%4];"
        : "=r"(r[0]), "=r"(r[1]), "=r"(r[2]), "=r"(r[3]) : "r"(addr));
}
__device__ __forceinline__ void mma16816(float* d, const uint32_t* a, const uint32_t* b) {
    asm volatile("mma.sync.aligned.m16n8k16.row.col.f32.bf16.bf16.f32 "
        "{%0,%1,%2,%3}, {%4,%5,%6,%7}, {%8,%9}, {%0,%1,%2,%3};"
        : "+f"(d[0]), "+f"(d[1]), "+f"(d[2]), "+f"(d[3])
        : "r"(a[0]), "r"(a[1]), "r"(a[2]), "r"(a[3]), "r"(b[0]), "r"(b[1]));
}
__device__ __forceinline__ void bf16_split(float v, uint16_t& hi, uint16_t& lo) {
    __nv_bfloat16 h = __float2bfloat16(v);
    __nv_bfloat16 l = __float2bfloat16(v - __bfloat162float(h));
    hi = __bfloat16_as_ushort(h);
    lo = __bfloat16_as_ushort(l);
}

// ---------------------------------------------------------------------------
// Kernel 1: xw[b,n,k] = sum_h inputs[b,n,h] * W_atom[h,k]
// ---------------------------------------------------------------------------
__global__ void __launch_bounds__(256, 4) xw_kernel(
    const float* __restrict__ inputs, const float* __restrict__ W_atom)
{
    __shared__ float s_in[4][HDIM];
    int row0 = blockIdx.x * 4;
    int t = threadIdx.x;
#pragma unroll
    for (int r = 0; r < 4; r++) s_in[r][t] = inputs[(row0 + r) * HDIM + t];
    __syncthreads();

    float a0 = 0.f, a1 = 0.f, a2 = 0.f, a3 = 0.f;
#pragma unroll 8
    for (int h = 0; h < HDIM; h++) {
        float w = W_atom[h * HDIM + t];
        a0 = fmaf(s_in[0][h], w, a0);
        a1 = fmaf(s_in[1][h], w, a1);
        a2 = fmaf(s_in[2][h], w, a2);
        a3 = fmaf(s_in[3][h], w, a3);
    }
    g_xw[(row0 + 0) * HDIM + t] = a0;
    g_xw[(row0 + 1) * HDIM + t] = a1;
    g_xw[(row0 + 2) * HDIM + t] = a2;
    g_xw[(row0 + 3) * HDIM + t] = a3;
}

// ---------------------------------------------------------------------------
// Kernel 2: split W_bin into bf16 hi/lo images [c8][h=256][n=32]
// ---------------------------------------------------------------------------
__global__ void __launch_bounds__(256) prep_w(const float* __restrict__ W_bin)
{
    int idx = blockIdx.x * 256 + threadIdx.x;   // 0..65535
    int c = idx >> 13;
    int r = idx & 8191;
    int h = r >> 5;
    int n = r & 31;
    float v = W_bin[h * HDIM + c * 32 + n];
    uint16_t hi, lo;
    bf16_split(v, hi, lo);
    g_Wh[c][h * 32 + n] = hi;
    g_Wl[c][h * 32 + n] = lo;
}

// ---------------------------------------------------------------------------
// Kernel 3: one CTA per (b,i,jhalf). 8 warps, warp tile m16 x n16.
//   2 CTAs/SM -> one CTA's memory phases overlap the other's HMMA phases.
// ---------------------------------------------------------------------------
extern __shared__ unsigned char smraw[];

__global__ void __launch_bounds__(NTHR, 2) main_kernel(
    const float* __restrict__ inputs,
    const float* __restrict__ bin_features,
    const float* __restrict__ b_bin,
    const float* __restrict__ w_score,
    float* __restrict__ out_pair)
{
    const int cta   = blockIdx.x;        // (b*128 + i)*2 + jhalf
    const int bi    = cta >> 1;
    const int jhalf = cta & 1;
    const int b     = bi >> 7;
    const int t     = threadIdx.x;
    const int warp  = t >> 5;            // 0..7
    const int lane  = t & 31;
    const int w_m   = warp >> 1;         // 0..3  (16 rows each)
    const int w_n   = warp & 1;          // 0..1  (16 cols each)
    const int g4    = lane >> 2, t4 = lane & 3;

    __nv_bfloat16* A_hi = (__nv_bfloat16*)smraw;              // [64][ASTR]
    __nv_bfloat16* A_lo = (__nv_bfloat16*)(smraw + OFF_ALO);
    float* base_s  = (float*)(smraw + MISC_OFF);   // xw_i + b_bin  [256]
    float* wsc_s   = base_s + HDIM;                // w_score       [256]
    float* ini_s   = wsc_s + HDIM;                 // inputs[b,i,:] [256]
    float* score_s = ini_s + HDIM;                 // [2][64]
    float* red_s   = score_s + 128;                // [8]

    // small smem fills
    base_s[t] = g_xw[bi * HDIM + t] + b_bin[t];
    wsc_s[t]  = w_score[t];
    ini_s[t]  = inputs[bi * HDIM + t];

    // A: this CTA's 64 rows of bin[b,i] -> bf16 hi/lo into padded smem
    const float4* gA = (const float4*)(bin_features
                        + (size_t)bi * NDIM * HDIM + (size_t)jhalf * 64 * HDIM);
#pragma unroll
    for (int r = 0; r < 16; r++) {
        int f = t + r * NTHR;            // 0..4095 float4
        int j = f >> 6, q = f & 63;
        float4 v = gA[f];
        uint16_t h0, l0, h1, l1, h2, l2, h3, l3;
        bf16_split(v.x, h0, l0); bf16_split(v.y, h1, l1);
        bf16_split(v.z, h2, l2); bf16_split(v.w, h3, l3);
        uint2 hv = { (uint32_t)h0 | ((uint32_t)h1 << 16),
                     (uint32_t)h2 | ((uint32_t)h3 << 16) };
        uint2 lv = { (uint32_t)l0 | ((uint32_t)l1 << 16),
                     (uint32_t)l2 | ((uint32_t)l3 << 16) };
        *(uint2*)&A_hi[j * ASTR + q * 4] = hv;
        *(uint2*)&A_lo[j * ASTR + q * 4] = lv;
    }

    const float4* gin  = (const float4*)(inputs + (size_t)b * NDIM * HDIM);
    float4*       gpr  = (float4*)(out_pair + (size_t)bi * NDIM * HDIM
                                   + (size_t)jhalf * 64 * HDIM);
    const float4* ini4 = (const float4*)ini_s;
    const float*  xwb  = g_xw + (size_t)(b * NDIM + jhalf * 64) * HDIM;

    const uint32_t sbase = smem_u32(smraw);
    const uint32_t sa_hi = sbase, sa_lo = sbase + OFF_ALO;
    const uint32_t sb_hi = sbase + OFF_BHI, sb_lo = sbase + OFF_BLO;
    const uint32_t a_lane = (uint32_t)(((w_m * 16 + (lane & 15)) * ASTR + ((lane >> 4) << 3)) * 2);
    const uint32_t b_lane = (uint32_t)(((lane & 15) * BSTR + w_n * 16 + ((lane >> 4) << 3)) * 2);

    // per-warp running scores for two j rows
    float sc0 = 0.f, sc1 = 0.f;
    const int j0 = w_m * 16 + g4;        // local row in [0,64)
    const int j1 = j0 + 8;

    for (int c = 0; c < 8; c++) {
        __syncthreads();   // prior chunk's MMAs done reading B

        // B chunk hi/lo via cp.async (packed [256][32] -> padded rows)
#pragma unroll
        for (int it = 0; it < 8; it++) {
            int idx  = t + it * NTHR;    // 0..2047
            int spl  = idx >> 10;
            int r    = idx & 1023;
            int h    = r >> 2;
            int seg  = r & 3;
            const unsigned short* src = spl ? &g_Wl[c][h * 32 + seg * 8]
                                            : &g_Wh[c][h * 32 + seg * 8];
            uint32_t dst = (spl ? sb_lo : sb_hi) + (uint32_t)(h * BSTR + seg * 8) * 2;
            cp_async16(dst, src);
        }
        asm volatile("cp.async.commit_group;" ::: "memory");

        // atom_pair: this chunk's eighth of this CTA's 64KB write
#pragma unroll
        for (int r = 0; r < 2; r++) {
            int g = (c << 9) + t + r * NTHR;     // 0..4095 over all chunks
            int j = g >> 6, q = g & 63;
            float4 a = ini4[q];
            float4 x = gin[((jhalf * 64 + j) << 6) + q];
            a.x += x.x; a.y += x.y; a.z += x.z; a.w += x.w;
            gpr[g] = a;
        }

        asm volatile("cp.async.wait_group 0;" ::: "memory");
        __syncthreads();

        float acc[2][4];
#pragma unroll
        for (int tn = 0; tn < 2; tn++)
#pragma unroll
            for (int e = 0; e < 4; e++) acc[tn][e] = 0.f;

#pragma unroll 2
        for (int ks = 0; ks < 16; ks++) {
            const int k0 = ks * 16;
            uint32_t ahi[4], alo[4], bhi[4], blo[4];
            {
                uint32_t off = a_lane + (uint32_t)(k0 * 2);
                ldsm_x4(ahi, sa_hi + off);
                ldsm_x4(alo, sa_lo + off);
            }
            {
                uint32_t off = b_lane + (uint32_t)(k0 * BSTR * 2);
                ldsm_x4_t(bhi, sb_hi + off);
                ldsm_x4_t(blo, sb_lo + off);
            }
#pragma unroll
            for (int tn = 0; tn < 2; tn++) {
                mma16816(acc[tn], ahi, &bhi[tn * 2]);
                mma16816(acc[tn], ahi, &blo[tn * 2]);
                mma16816(acc[tn], alo, &bhi[tn * 2]);
            }
        }

        // fused epilogue on fragments
        const int Cb = c * 32 + w_n * 16;
        float p0 = 0.f, p1 = 0.f;
#pragma unroll
        for (int tn = 0; tn < 2; tn++) {
            const int n0 = Cb + tn * 8 + t4 * 2;
            float2 bw = *(const float2*)&base_s[n0];
            float2 wv = *(const float2*)&wsc_s[n0];
            float2 x0 = *(const float2*)&xwb[(size_t)j0 * HDIM + n0];
            float2 x1 = *(const float2*)&xwb[(size_t)j1 * HDIM + n0];
            const float* a = acc[tn];
            p0 = fmaf(fmaxf(a[0] + bw.x + x0.x, 0.f), wv.x, p0);
            p0 = fmaf(fmaxf(a[1] + bw.y + x0.y, 0.f), wv.y, p0);
            p1 = fmaf(fmaxf(a[2] + bw.x + x1.x, 0.f), wv.x, p1);
            p1 = fmaf(fmaxf(a[3] + bw.y + x1.y, 0.f), wv.y, p1);
        }
        p0 += __shfl_xor_sync(0xffffffffu, p0, 1);
        p0 += __shfl_xor_sync(0xffffffffu, p0, 2);
        p1 += __shfl_xor_sync(0xffffffffu, p1, 1);
        p1 += __shfl_xor_sync(0xffffffffu, p1, 2);
        sc0 += p0;
        sc1 += p1;
    }

    if (t4 == 0) {
        score_s[w_n * 64 + j0] = sc0;
        score_s[w_n * 64 + j1] = sc1;
    }

    __syncthreads();
    // partial sum over this CTA's 64 j rows
    if (t < 64) {
        float S = score_s[t] + score_s[64 + t];
        S += __shfl_xor_sync(0xffffffffu, S, 16);
        S += __shfl_xor_sync(0xffffffffu, S, 8);
        S += __shfl_xor_sync(0xffffffffu, S, 4);
        S += __shfl_xor_sync(0xffffffffu, S, 2);
        S += __shfl_xor_sync(0xffffffffu, S, 1);
        if ((t & 31) == 0) red_s[t >> 5] = S;
    }
    __syncthreads();
    if (t == 0) g_part[cta] = red_s[0] + red_s[1];
}

// ---------------------------------------------------------------------------
// Kernel 4: out_ctx[bi,h] = inputs[bi,h] * (part0 + part1 + N*b_score)
// ---------------------------------------------------------------------------
__global__ void __launch_bounds__(256) ctx_kernel(
    const float* __restrict__ inputs,
    const float* __restrict__ b_score,
    float* __restrict__ out_ctx)
{
    int bi = blockIdx.x;
    float S = g_part[2 * bi] + g_part[2 * bi + 1] + (float)NDIM * b_score[0];
    out_ctx[bi * HDIM + threadIdx.x] = inputs[bi * HDIM + threadIdx.x] * S;
}

// ---------------------------------------------------------------------------
extern "C" void kernel_launch(void* const* d_in, const int* in_sizes, int n_in,
                              void* d_out, int out_size)
{
    const float* inputs       = (const float*)d_in[0];
    const float* bin_features = (const float*)d_in[1];
    const float* W_atom       = (const float*)d_in[2];
    const float* W_bin        = (const float*)d_in[3];
    const float* b_bin        = (const float*)d_in[4];
    const float* w_score      = (const float*)d_in[5];
    const float* b_score      = (const float*)d_in[6];

    float* out_ctx  = (float*)d_out;                   // [B,N,H]
    float* out_pair = out_ctx + BDIM * NDIM * HDIM;    // [B,N,N,H]

    static bool attr_set = false;
    if (!attr_set) {
        cudaFuncSetAttribute(main_kernel, cudaFuncAttributeMaxDynamicSharedMemorySize,
                             SMEM_REQ);
        attr_set = true;
    }

    xw_kernel<<<(BDIM * NDIM) / 4, 256>>>(inputs, W_atom);
    prep_w<<<256, 256>>>(W_bin);
    main_kernel<<<2 * BDIM * NDIM, NTHR, SMEM_REQ>>>(
        inputs, bin_features, b_bin, w_score, out_pair);
    ctx_kernel<<<BDIM * NDIM, 256>>>(inputs, b_score, out_ctx);
}

// round 7
// speedup vs baseline: 1.7818x; 1.7818x over previous
#include <cuda_runtime.h>
#include <cuda_fp16.h>
#include <cstdint>

#define BDIM 16
#define NDIM 128
#define HDIM 256

#define ASTR 264     // A smem row stride (fp16), padded: ldmatrix conflict-free
#define BSTR 264     // B smem row stride (fp16), padded

#define A_BYTES (128 * ASTR * 2)     // 67584
#define B_BYTES (256 * BSTR * 2)     // 135168
#define MISC_OFF (A_BYTES + B_BYTES) // 202752
#define SMEM_REQ (MISC_OFF + 4352)   // misc needs 4128B

#define NTHR 512

// scratch
__device__ float g_xw[BDIM * NDIM * HDIM];            // inputs @ W_atom
__device__ __align__(16) __half g_Wf[HDIM * HDIM];    // fp16 image of W_bin

// ---------------------------------------------------------------------------
__device__ __forceinline__ uint32_t smem_u32(const void* p) {
    uint32_t a;
    asm("{ .reg .u64 t; cvta.to.shared.u64 t, %1; cvt.u32.u64 %0, t; }" : "=r"(a) : "l"(p));
    return a;
}
__device__ __forceinline__ void cp_async16(uint32_t dst, const void* src) {
    asm volatile("cp.async.cg.shared.global [%0], [%1], 16;" :: "r"(dst), "l"(src));
}
__device__ __forceinline__ void ldsm_x4(uint32_t* r, uint32_t addr) {
    asm volatile("ldmatrix.sync.aligned.m8n8.x4.shared.b16 {%0,%1,%2,%3}, [%4];"
        : "=r"(r[0]), "=r"(r[1]), "=r"(r[2]), "=r"(r[3]) : "r"(addr));
}
__device__ __forceinline__ void ldsm_x4_t(uint32_t* r, uint32_t addr) {
    asm volatile("ldmatrix.sync.aligned.m8n8.x4.trans.shared.b16 {%0,%1,%2,%3}, [%4];"
        : "=r"(r[0]), "=r"(r[1]), "=r"(r[2]), "=r"(r[3]) : "r"(addr));
}
__device__ __forceinline__ void mma16816(float* d, const uint32_t* a, const uint32_t* b) {
    asm volatile("mma.sync.aligned.m16n8k16.row.col.f32.f16.f16.f32 "
        "{%0,%1,%2,%3}, {%4,%5,%6,%7}, {%8,%9}, {%0,%1,%2,%3};"
        : "+f"(d[0]), "+f"(d[1]), "+f"(d[2]), "+f"(d[3])
        : "r"(a[0]), "r"(a[1]), "r"(a[2]), "r"(a[3]), "r"(b[0]), "r"(b[1]));
}

// ---------------------------------------------------------------------------
// Kernel 1: xw[b,n,k] = sum_h inputs[b,n,h] * W_atom[h,k]
// ---------------------------------------------------------------------------
__global__ void __launch_bounds__(256, 4) xw_kernel(
    const float* __restrict__ inputs, const float* __restrict__ W_atom)
{
    __shared__ float s_in[4][HDIM];
    int row0 = blockIdx.x * 4;
    int t = threadIdx.x;
#pragma unroll
    for (int r = 0; r < 4; r++) s_in[r][t] = inputs[(row0 + r) * HDIM + t];
    __syncthreads();

    float a0 = 0.f, a1 = 0.f, a2 = 0.f, a3 = 0.f;
#pragma unroll 8
    for (int h = 0; h < HDIM; h++) {
        float w = W_atom[h * HDIM + t];
        a0 = fmaf(s_in[0][h], w, a0);
        a1 = fmaf(s_in[1][h], w, a1);
        a2 = fmaf(s_in[2][h], w, a2);
        a3 = fmaf(s_in[3][h], w, a3);
    }
    g_xw[(row0 + 0) * HDIM + t] = a0;
    g_xw[(row0 + 1) * HDIM + t] = a1;
    g_xw[(row0 + 2) * HDIM + t] = a2;
    g_xw[(row0 + 3) * HDIM + t] = a3;
}

// ---------------------------------------------------------------------------
// Kernel 2: W_bin fp32 -> fp16 image (packed [h][n])
// ---------------------------------------------------------------------------
__global__ void __launch_bounds__(256) prep_w(const float* __restrict__ W_bin)
{
    int f = blockIdx.x * 256 + threadIdx.x;   // 0..16383 float4
    float4 v = *(const float4*)&W_bin[f * 4];
    __half2 p0 = __floats2half2_rn(v.x, v.y);
    __half2 p1 = __floats2half2_rn(v.z, v.w);
    *(uint2*)&g_Wf[f * 4] = make_uint2(*(uint32_t*)&p0, *(uint32_t*)&p1);
}

// ---------------------------------------------------------------------------
// Kernel 3: one CTA per (b,i). 16 warps m16 x n32. Single fp16 HMMA product.
//   A (128x256) and B (256x256) both smem-resident; no syncs in mainloop.
// ---------------------------------------------------------------------------
extern __shared__ unsigned char smraw[];

__global__ void __launch_bounds__(NTHR, 1) main_kernel(
    const float* __restrict__ inputs,
    const float* __restrict__ bin_features,
    const float* __restrict__ b_bin,
    const float* __restrict__ w_score,
    const float* __restrict__ b_score,
    float* __restrict__ out_ctx,
    float* __restrict__ out_pair)
{
    const int bi   = blockIdx.x;         // b*128 + i
    const int b    = bi >> 7;
    const int t    = threadIdx.x;
    const int warp = t >> 5;             // 0..15
    const int lane = t & 31;
    const int w_m  = warp >> 1;          // 0..7  (16 rows each)
    const int w_n  = warp & 1;           // 0..1  (32 cols each within 64-chunk)
    const int g4   = lane >> 2, t4 = lane & 3;

    __half* A_s = (__half*)smraw;                       // [128][ASTR]
    __half* B_s = (__half*)(smraw + A_BYTES);           // [256][BSTR]
    float* base_s  = (float*)(smraw + MISC_OFF);   // xw_i + b_bin  [256]
    float* wsc_s   = base_s + HDIM;                // w_score       [256]
    float* ini_s   = wsc_s + HDIM;                 // inputs[b,i,:] [256]
    float* score_s = ini_s + HDIM;                 // [2][128]
    float* red_s   = score_s + 2 * NDIM;           // [8]

    const uint32_t sbase = smem_u32(smraw);
    const uint32_t sA = sbase, sB = sbase + A_BYTES;

    // B: cp.async packed fp16 [256][256] -> padded rows (16 segs/thread)
#pragma unroll
    for (int it = 0; it < 16; it++) {
        int seg = t + it * NTHR;          // 0..8191 (16B segments)
        int h = seg >> 5, q = seg & 31;
        cp_async16(sB + (uint32_t)(h * BSTR + q * 8) * 2, &g_Wf[h * HDIM + q * 8]);
    }
    asm volatile("cp.async.commit_group;" ::: "memory");

    // small smem fills
    if (t < HDIM) {
        base_s[t] = g_xw[bi * HDIM + t] + b_bin[t];
        wsc_s[t]  = w_score[t];
        ini_s[t]  = inputs[bi * HDIM + t];
    }

    // A: bin[b,i] fp32 -> fp16 into padded smem
    const float4* gA = (const float4*)(bin_features + (size_t)bi * NDIM * HDIM);
#pragma unroll
    for (int r = 0; r < 16; r++) {
        int f = t + r * NTHR;            // 0..8191 float4
        int j = f >> 6, q = f & 63;
        float4 v = gA[f];
        __half2 p0 = __floats2half2_rn(v.x, v.y);
        __half2 p1 = __floats2half2_rn(v.z, v.w);
        *(uint2*)&A_s[j * ASTR + q * 4] = make_uint2(*(uint32_t*)&p0, *(uint32_t*)&p1);
    }

    asm volatile("cp.async.wait_group 0;" ::: "memory");
    __syncthreads();   // A, B, ini_s, base_s, wsc_s all ready

    const float4* gin  = (const float4*)(inputs + (size_t)b * NDIM * HDIM);
    float4*       gpr  = (float4*)(out_pair + (size_t)bi * NDIM * HDIM);
    const float4* ini4 = (const float4*)ini_s;
    const float*  xwb  = g_xw + (size_t)(b * NDIM) * HDIM;

    const uint32_t a_lane = (uint32_t)(((w_m * 16 + (lane & 15)) * ASTR + ((lane >> 4) << 3)) * 2);
    const uint32_t b_lane = (uint32_t)(((lane & 15) * BSTR + w_n * 32 + ((lane >> 4) << 3)) * 2);

    // per-warp running scores for two j rows (j0 = w_m*16+g4, j1 = j0+8)
    float sc0 = 0.f, sc1 = 0.f;
    const int j0 = w_m * 16 + g4;
    const int j1 = j0 + 8;

    for (int c = 0; c < 4; c++) {
        // atom_pair: this chunk's quarter of the 128KB write (overlaps MMA)
#pragma unroll
        for (int r = 0; r < 4; r++) {
            int g = (c << 11) + t + r * NTHR;
            int j = g >> 6, q = g & 63;
            float4 a = ini4[q];
            float4 x = gin[(j << 6) + q];
            a.x += x.x; a.y += x.y; a.z += x.z; a.w += x.w;
            gpr[g] = a;
        }

        float acc[4][4];
#pragma unroll
        for (int tn = 0; tn < 4; tn++)
#pragma unroll
            for (int e = 0; e < 4; e++) acc[tn][e] = 0.f;

        const uint32_t b_chunk = b_lane + (uint32_t)(c * 64 * 2);
#pragma unroll 4
        for (int ks = 0; ks < 16; ks++) {
            const int k0 = ks * 16;
            uint32_t av[4], bv[2][4];
            ldsm_x4(av, sA + a_lane + (uint32_t)(k0 * 2));
#pragma unroll
            for (int nt = 0; nt < 2; nt++)
                ldsm_x4_t(bv[nt], sB + b_chunk + (uint32_t)((k0 * BSTR + nt * 16) * 2));
#pragma unroll
            for (int tn = 0; tn < 4; tn++) {
                const int nt = tn >> 1, hf = (tn & 1) * 2;
                mma16816(acc[tn], av, &bv[nt][hf]);
            }
        }

        // fused epilogue on fragments: running score in registers
        const int Cb = c * 64 + w_n * 32;
        float p0 = 0.f, p1 = 0.f;
#pragma unroll
        for (int tn = 0; tn < 4; tn++) {
            const int n0 = Cb + tn * 8 + t4 * 2;
            float2 bw = *(const float2*)&base_s[n0];
            float2 wv = *(const float2*)&wsc_s[n0];
            float2 x0 = *(const float2*)&xwb[(size_t)j0 * HDIM + n0];
            float2 x1 = *(const float2*)&xwb[(size_t)j1 * HDIM + n0];
            const float* a = acc[tn];
            p0 = fmaf(fmaxf(a[0] + bw.x + x0.x, 0.f), wv.x, p0);
            p0 = fmaf(fmaxf(a[1] + bw.y + x0.y, 0.f), wv.y, p0);
            p1 = fmaf(fmaxf(a[2] + bw.x + x1.x, 0.f), wv.x, p1);
            p1 = fmaf(fmaxf(a[3] + bw.y + x1.y, 0.f), wv.y, p1);
        }
        p0 += __shfl_xor_sync(0xffffffffu, p0, 1);
        p0 += __shfl_xor_sync(0xffffffffu, p0, 2);
        p1 += __shfl_xor_sync(0xffffffffu, p1, 1);
        p1 += __shfl_xor_sync(0xffffffffu, p1, 2);
        sc0 += p0;
        sc1 += p1;
    }

    // one plain store per (warp-half, j row) — no atomics
    if (t4 == 0) {
        score_s[w_n * NDIM + j0] = sc0;
        score_s[w_n * NDIM + j1] = sc1;
    }

    __syncthreads();
    if (t < NDIM) {
        float S = score_s[t] + score_s[NDIM + t];
        S += __shfl_xor_sync(0xffffffffu, S, 16);
        S += __shfl_xor_sync(0xffffffffu, S, 8);
        S += __shfl_xor_sync(0xffffffffu, S, 4);
        S += __shfl_xor_sync(0xffffffffu, S, 2);
        S += __shfl_xor_sync(0xffffffffu, S, 1);
        if ((t & 31) == 0) red_s[t >> 5] = S;
    }
    __syncthreads();
    if (t == 0)
        red_s[4] = red_s[0] + red_s[1] + red_s[2] + red_s[3]
                 + (float)NDIM * b_score[0];
    __syncthreads();

    if (t < HDIM)
        out_ctx[bi * HDIM + t] = ini_s[t] * red_s[4];
}

// ---------------------------------------------------------------------------
extern "C" void kernel_launch(void* const* d_in, const int* in_sizes, int n_in,
                              void* d_out, int out_size)
{
    const float* inputs       = (const float*)d_in[0];
    const float* bin_features = (const float*)d_in[1];
    const float* W_atom       = (const float*)d_in[2];
    const float* W_bin        = (const float*)d_in[3];
    const float* b_bin        = (const float*)d_in[4];
    const float* w_score      = (const float*)d_in[5];
    const float* b_score      = (const float*)d_in[6];

    float* out_ctx  = (float*)d_out;                   // [B,N,H]
    float* out_pair = out_ctx + BDIM * NDIM * HDIM;    // [B,N,N,H]

    static bool attr_set = false;
    if (!attr_set) {
        cudaFuncSetAttribute(main_kernel, cudaFuncAttributeMaxDynamicSharedMemorySize,
                             SMEM_REQ);
        attr_set = true;
    }

    xw_kernel<<<(BDIM * NDIM) / 4, 256>>>(inputs, W_atom);
    prep_w<<<64, 256>>>(W_bin);
    main_kernel<<<BDIM * NDIM, NTHR, SMEM_REQ>>>(
        inputs, bin_features, b_bin, w_score, b_score, out_ctx, out_pair);
}

// round 8
// speedup vs baseline: 1.9673x; 1.1041x over previous
#include <cuda_runtime.h>
#include <cuda_fp16.h>
#include <cstdint>

#define BDIM 16
#define NDIM 128
#define HDIM 256

#define ASTR 264     // A smem row stride (fp16), padded: ldmatrix conflict-free
#define BSTR 40      // B smem row stride (fp16): 32 n-cols + 8 pad

#define A_BYTES (128 * ASTR * 2)     // 67584
#define B_BYTES (256 * BSTR * 2)     // 20480
#define MISC_OFF (A_BYTES + B_BYTES) // 88064
#define SMEM_REQ (MISC_OFF + 4800)   // misc needs 4640B

#define NTHR 256

// scratch
__device__ float g_xw[BDIM * NDIM * HDIM];            // inputs @ W_atom
__device__ __align__(16) __half g_Wf[HDIM * HDIM];    // fp16 image of W_bin

// ---------------------------------------------------------------------------
__device__ __forceinline__ uint32_t smem_u32(const void* p) {
    uint32_t a;
    asm("{ .reg .u64 t; cvta.to.shared.u64 t, %1; cvt.u32.u64 %0, t; }" : "=r"(a) : "l"(p));
    return a;
}
__device__ __forceinline__ void cp_async16(uint32_t dst, const void* src) {
    asm volatile("cp.async.cg.shared.global [%0], [%1], 16;" :: "r"(dst), "l"(src));
}
__device__ __forceinline__ void ldsm_x4(uint32_t* r, uint32_t addr) {
    asm volatile("ldmatrix.sync.aligned.m8n8.x4.shared.b16 {%0,%1,%2,%3}, [%4];"
        : "=r"(r[0]), "=r"(r[1]), "=r"(r[2]), "=r"(r[3]) : "r"(addr));
}
__device__ __forceinline__ void ldsm_x4_t(uint32_t* r, uint32_t addr) {
    asm volatile("ldmatrix.sync.aligned.m8n8.x4.trans.shared.b16 {%0,%1,%2,%3}, [%4];"
        : "=r"(r[0]), "=r"(r[1]), "=r"(r[2]), "=r"(r[3]) : "r"(addr));
}
__device__ __forceinline__ void mma16816(float* d, const uint32_t* a, const uint32_t* b) {
    asm volatile("mma.sync.aligned.m16n8k16.row.col.f32.f16.f16.f32 "
        "{%0,%1,%2,%3}, {%4,%5,%6,%7}, {%8,%9}, {%0,%1,%2,%3};"
        : "+f"(d[0]), "+f"(d[1]), "+f"(d[2]), "+f"(d[3])
        : "r"(a[0]), "r"(a[1]), "r"(a[2]), "r"(a[3]), "r"(b[0]), "r"(b[1]));
}

// ---------------------------------------------------------------------------
// Kernel 1: xw[b,n,k] = sum_h inputs[b,n,h] * W_atom[h,k]
// ---------------------------------------------------------------------------
__global__ void __launch_bounds__(256, 4) xw_kernel(
    const float* __restrict__ inputs, const float* __restrict__ W_atom)
{
    __shared__ float s_in[4][HDIM];
    int row0 = blockIdx.x * 4;
    int t = threadIdx.x;
#pragma unroll
    for (int r = 0; r < 4; r++) s_in[r][t] = inputs[(row0 + r) * HDIM + t];
    __syncthreads();

    float a0 = 0.f, a1 = 0.f, a2 = 0.f, a3 = 0.f;
#pragma unroll 8
    for (int h = 0; h < HDIM; h++) {
        float w = W_atom[h * HDIM + t];
        a0 = fmaf(s_in[0][h], w, a0);
        a1 = fmaf(s_in[1][h], w, a1);
        a2 = fmaf(s_in[2][h], w, a2);
        a3 = fmaf(s_in[3][h], w, a3);
    }
    g_xw[(row0 + 0) * HDIM + t] = a0;
    g_xw[(row0 + 1) * HDIM + t] = a1;
    g_xw[(row0 + 2) * HDIM + t] = a2;
    g_xw[(row0 + 3) * HDIM + t] = a3;
}

// ---------------------------------------------------------------------------
// Kernel 2: W_bin fp32 -> fp16 image (packed [h][n])
// ---------------------------------------------------------------------------
__global__ void __launch_bounds__(256) prep_w(const float* __restrict__ W_bin)
{
    int f = blockIdx.x * 256 + threadIdx.x;   // 0..16383 float4
    float4 v = *(const float4*)&W_bin[f * 4];
    __half2 p0 = __floats2half2_rn(v.x, v.y);
    __half2 p1 = __floats2half2_rn(v.z, v.w);
    *(uint2*)&g_Wf[f * 4] = make_uint2(*(uint32_t*)&p0, *(uint32_t*)&p1);
}

// ---------------------------------------------------------------------------
// Kernel 3: one CTA per (b,i). 256 thr, 8 warps (m16 x n32 tile), 2 CTAs/SM.
//   One CTA's memory phases overlap the other's HMMA phases.
// ---------------------------------------------------------------------------
extern __shared__ unsigned char smraw[];

__global__ void __launch_bounds__(NTHR, 2) main_kernel(
    const float* __restrict__ inputs,
    const float* __restrict__ bin_features,
    const float* __restrict__ b_bin,
    const float* __restrict__ w_score,
    const float* __restrict__ b_score,
    float* __restrict__ out_ctx,
    float* __restrict__ out_pair)
{
    const int bi   = blockIdx.x;         // b*128 + i
    const int b    = bi >> 7;
    const int t    = threadIdx.x;
    const int warp = t >> 5;             // 0..7  (16 j-rows each)
    const int lane = t & 31;
    const int g4   = lane >> 2, t4 = lane & 3;

    __half* A_s = (__half*)smraw;                       // [128][ASTR]
    float* base_s  = (float*)(smraw + MISC_OFF);   // xw_i + b_bin  [256]
    float* wsc_s   = base_s + HDIM;                // w_score       [256]
    float* ini_s   = wsc_s + HDIM;                 // inputs[b,i,:] [256]
    float* score_s = ini_s + HDIM;                 // [128]
    float* red_s   = score_s + NDIM;               // [8]

    const uint32_t sbase = smem_u32(smraw);
    const uint32_t sA = sbase, sB = sbase + A_BYTES;

    // small smem fills
    base_s[t] = g_xw[bi * HDIM + t] + b_bin[t];
    wsc_s[t]  = w_score[t];
    ini_s[t]  = inputs[bi * HDIM + t];

    // A: bin[b,i] fp32 -> fp16 into padded smem
    const float4* gA = (const float4*)(bin_features + (size_t)bi * NDIM * HDIM);
#pragma unroll
    for (int r = 0; r < 32; r++) {
        int f = t + r * NTHR;            // 0..8191 float4
        int j = f >> 6, q = f & 63;
        float4 v = gA[f];
        __half2 p0 = __floats2half2_rn(v.x, v.y);
        __half2 p1 = __floats2half2_rn(v.z, v.w);
        *(uint2*)&A_s[j * ASTR + q * 4] = make_uint2(*(uint32_t*)&p0, *(uint32_t*)&p1);
    }

    const float4* gin  = (const float4*)(inputs + (size_t)b * NDIM * HDIM);
    float4*       gpr  = (float4*)(out_pair + (size_t)bi * NDIM * HDIM);
    const float4* ini4 = (const float4*)ini_s;
    const float*  xwb  = g_xw + (size_t)(b * NDIM) * HDIM;

    const uint32_t a_lane = (uint32_t)(((warp * 16 + (lane & 15)) * ASTR + ((lane >> 4) << 3)) * 2);
    const uint32_t b_lane = (uint32_t)(((lane & 15) * BSTR + ((lane >> 4) << 3)) * 2);

    // per-warp running scores for two j rows
    float sc0 = 0.f, sc1 = 0.f;
    const int j0 = warp * 16 + g4;
    const int j1 = j0 + 8;

    for (int c = 0; c < 8; c++) {
        __syncthreads();   // prior chunk's MMAs done reading B (A/misc on c=0)

        // B chunk [256k][32n] via cp.async (4 segs/thread)
#pragma unroll
        for (int it = 0; it < 4; it++) {
            int idx = t + it * NTHR;     // 0..1023
            int h = idx >> 2, seg = idx & 3;
            cp_async16(sB + (uint32_t)(h * BSTR + seg * 8) * 2,
                       &g_Wf[h * HDIM + c * 32 + seg * 8]);
        }
        asm volatile("cp.async.commit_group;" ::: "memory");

        // atom_pair: this chunk's eighth of the 128KB write (overlaps)
#pragma unroll
        for (int r = 0; r < 4; r++) {
            int g = (c << 10) + t + r * NTHR;
            int j = g >> 6, q = g & 63;
            float4 a = ini4[q];
            float4 x = gin[(j << 6) + q];
            a.x += x.x; a.y += x.y; a.z += x.z; a.w += x.w;
            gpr[g] = a;
        }

        asm volatile("cp.async.wait_group 0;" ::: "memory");
        __syncthreads();

        float acc[4][4];
#pragma unroll
        for (int tn = 0; tn < 4; tn++)
#pragma unroll
            for (int e = 0; e < 4; e++) acc[tn][e] = 0.f;

#pragma unroll 4
        for (int ks = 0; ks < 16; ks++) {
            const int k0 = ks * 16;
            uint32_t av[4], bv[2][4];
            ldsm_x4(av, sA + a_lane + (uint32_t)(k0 * 2));
#pragma unroll
            for (int nt = 0; nt < 2; nt++)
                ldsm_x4_t(bv[nt], sB + b_lane + (uint32_t)((k0 * BSTR + nt * 16) * 2));
#pragma unroll
            for (int tn = 0; tn < 4; tn++) {
                const int nt = tn >> 1, hf = (tn & 1) * 2;
                mma16816(acc[tn], av, &bv[nt][hf]);
            }
        }

        // fused epilogue on fragments
        const int Cb = c * 32;
        float p0 = 0.f, p1 = 0.f;
#pragma unroll
        for (int tn = 0; tn < 4; tn++) {
            const int n0 = Cb + tn * 8 + t4 * 2;
            float2 bw = *(const float2*)&base_s[n0];
            float2 wv = *(const float2*)&wsc_s[n0];
            float2 x0 = *(const float2*)&xwb[(size_t)j0 * HDIM + n0];
            float2 x1 = *(const float2*)&xwb[(size_t)j1 * HDIM + n0];
            const float* a = acc[tn];
            p0 = fmaf(fmaxf(a[0] + bw.x + x0.x, 0.f), wv.x, p0);
            p0 = fmaf(fmaxf(a[1] + bw.y + x0.y, 0.f), wv.y, p0);
            p1 = fmaf(fmaxf(a[2] + bw.x + x1.x, 0.f), wv.x, p1);
            p1 = fmaf(fmaxf(a[3] + bw.y + x1.y, 0.f), wv.y, p1);
        }
        p0 += __shfl_xor_sync(0xffffffffu, p0, 1);
        p0 += __shfl_xor_sync(0xffffffffu, p0, 2);
        p1 += __shfl_xor_sync(0xffffffffu, p1, 1);
        p1 += __shfl_xor_sync(0xffffffffu, p1, 2);
        sc0 += p0;
        sc1 += p1;
    }

    if (t4 == 0) {
        score_s[j0] = sc0;
        score_s[j1] = sc1;
    }

    __syncthreads();
    if (t < NDIM) {
        float S = score_s[t];
        S += __shfl_xor_sync(0xffffffffu, S, 16);
        S += __shfl_xor_sync(0xffffffffu, S, 8);
        S += __shfl_xor_sync(0xffffffffu, S, 4);
        S += __shfl_xor_sync(0xffffffffu, S, 2);
        S += __shfl_xor_sync(0xffffffffu, S, 1);
        if ((t & 31) == 0) red_s[t >> 5] = S;
    }
    __syncthreads();
    if (t == 0)
        red_s[4] = red_s[0] + red_s[1] + red_s[2] + red_s[3]
                 + (float)NDIM * b_score[0];
    __syncthreads();

    out_ctx[bi * HDIM + t] = ini_s[t] * red_s[4];
}

// ---------------------------------------------------------------------------
extern "C" void kernel_launch(void* const* d_in, const int* in_sizes, int n_in,
                              void* d_out, int out_size)
{
    const float* inputs       = (const float*)d_in[0];
    const float* bin_features = (const float*)d_in[1];
    const float* W_atom       = (const float*)d_in[2];
    const float* W_bin        = (const float*)d_in[3];
    const float* b_bin        = (const float*)d_in[4];
    const float* w_score      = (const float*)d_in[5];
    const float* b_score      = (const float*)d_in[6];

    float* out_ctx  = (float*)d_out;                   // [B,N,H]
    float* out_pair = out_ctx + BDIM * NDIM * HDIM;    // [B,N,N,H]

    static bool attr_set = false;
    if (!attr_set) {
        cudaFuncSetAttribute(main_kernel, cudaFuncAttributeMaxDynamicSharedMemorySize,
                             SMEM_REQ);
        attr_set = true;
    }

    xw_kernel<<<(BDIM * NDIM) / 4, 256>>>(inputs, W_atom);
    prep_w<<<64, 256>>>(W_bin);
    main_kernel<<<BDIM * NDIM, NTHR, SMEM_REQ>>>(
        inputs, bin_features, b_bin, w_score, b_score, out_ctx, out_pair);
}